// round 17
// baseline (speedup 1.0000x reference)
#include <cuda_runtime.h>
#include <math.h>

#define DIM 64
#define MAXN 200000
#define MAXE 1600000

// Scratch (allocation-free rule: __device__ globals).
__device__ float  g_bufA[(size_t)MAXN * DIM];
__device__ float  g_bufB[(size_t)MAXN * DIM];
__device__ float2 g_edge [MAXE];   // packed (col-as-float-bits, val)          — layers 2,3
__device__ float2 g_edge1[MAXE];   // packed (col-as-float-bits, val*scale[c]) — layer 1
__device__ float  g_scale[MAXN];   // logmap0 per-node scale
__device__ int    g_rowptr[MAXN + 1];

__device__ __forceinline__ float warpAllSum(float v) {
#pragma unroll
    for (int o = 16; o; o >>= 1) v += __shfl_xor_sync(0xffffffffu, v, o);
    return v;
}

// butterfly within a 16-lane half (offsets 8,4,2,1 stay inside the half)
__device__ __forceinline__ float halfAllSum(float v) {
#pragma unroll
    for (int o = 8; o; o >>= 1) v += __shfl_xor_sync(0xffffffffu, v, o);
    return v;
}

// ---------------------------------------------------------------------------
// scale[n] = acosh(max(w0,1+eps)) / max(||w[1:]||, 1e-15)   (logmap0 scalar)
// warp per node; 51MB read, 0.8MB write.
// ---------------------------------------------------------------------------
__global__ void k_scale(const float* __restrict__ w, int N) {
    int warp = (blockIdx.x * blockDim.x + threadIdx.x) >> 5;
    int lane = threadIdx.x & 31;
    if (warp >= N) return;
    const float2 v = *(const float2*)(w + (size_t)warp * DIM + lane * 2);
    float y0 = (lane == 0) ? 0.0f : v.x;
    float y1 = v.y;
    float n2 = warpAllSum(y0 * y0 + y1 * y1);
    float norm = fmaxf(sqrtf(n2), 1e-15f);
    float w0 = __shfl_sync(0xffffffffu, v.x, 0);
    float theta = fmaxf(w0, 1.0f + 1e-7f);
    if (lane == 0) g_scale[warp] = acoshf(theta) / norm;
}

// ---------------------------------------------------------------------------
// pack edges (both variants), build rowptr, zero the output.
// ---------------------------------------------------------------------------
__global__ void k_pack(const int* __restrict__ row, const int* __restrict__ col,
                       const float* __restrict__ vals,
                       int N, int E, float* __restrict__ out, int out_size) {
    int i = blockIdx.x * blockDim.x + threadIdx.x;
    if (i < out_size) out[i] = 0.0f;
    if (i < E) {
        int   c = __ldg(&col[i]);
        float v = __ldg(&vals[i]);
        float2 p;
        p.x = __int_as_float(c);
        p.y = v;
        g_edge[i] = p;
        p.y = v * __ldg(&g_scale[c]);
        g_edge1[i] = p;
    }
    if (i <= N) {
        int lo = 0, hi = E;
        while (lo < hi) {
            int m = (lo + hi) >> 1;
            if (__ldg(&row[m]) < i) lo = m + 1; else hi = m;
        }
        g_rowptr[i] = lo;
    }
}

// ---------------------------------------------------------------------------
// Row gather, HALF-WARP PER ROW, lane owns dims [4q..4q+3]. No reduction.
// Packed edge loads: ONE LDG.64 per edge. 2-edge unroll.
// ZERO0: mask x-component for q==0 (layer 1 gathers raw weight; x_t dim0 = 0)
// ---------------------------------------------------------------------------
template <bool ZERO0>
__device__ __forceinline__ float4 half_row_gather(const float* __restrict__ in,
                                                  const float2* __restrict__ edge,
                                                  int s, int e, int q) {
    float4 sum = make_float4(0.0f, 0.0f, 0.0f, 0.0f);
    bool mask0 = ZERO0 && (q == 0);
    int k = s;
    for (; k + 2 <= e; k += 2) {
        float2 p0 = __ldg(&edge[k]);
        float2 p1 = __ldg(&edge[k + 1]);
        int   c0 = __float_as_int(p0.x);
        int   c1 = __float_as_int(p1.x);
        float v0 = p0.y, v1 = p1.y;
        float4 x0 = *(const float4*)(in + (size_t)c0 * DIM);
        float4 x1 = *(const float4*)(in + (size_t)c1 * DIM);
        if (mask0) { x0.x = 0.0f; x1.x = 0.0f; }
        sum.x = fmaf(v0, x0.x, sum.x); sum.y = fmaf(v0, x0.y, sum.y);
        sum.z = fmaf(v0, x0.z, sum.z); sum.w = fmaf(v0, x0.w, sum.w);
        sum.x = fmaf(v1, x1.x, sum.x); sum.y = fmaf(v1, x1.y, sum.y);
        sum.z = fmaf(v1, x1.z, sum.z); sum.w = fmaf(v1, x1.w, sum.w);
    }
    if (k < e) {
        float2 p = __ldg(&edge[k]);
        int   c = __float_as_int(p.x);
        float v = p.y;
        float4 x = *(const float4*)(in + (size_t)c * DIM);
        if (mask0) x.x = 0.0f;
        sum.x = fmaf(v, x.x, sum.x); sum.y = fmaf(v, x.y, sum.y);
        sum.z = fmaf(v, x.z, sum.z); sum.w = fmaf(v, x.w, sum.w);
    }
    return sum;
}

// ---------------------------------------------------------------------------
// Layer 1: gathers raw weight with scaled edge weights (g_edge1) -> bufB (h1)
// warp handles rows {2w, 2w+1} (one per half).
// ---------------------------------------------------------------------------
__global__ void __launch_bounds__(256, 8)
k_spmv1(const float* __restrict__ weight, int N) {
    int warp = (blockIdx.x * blockDim.x + threadIdx.x) >> 5;
    int lane = threadIdx.x & 31;
    int half = lane >> 4, q = lane & 15;
    int row = warp * 2 + half;
    bool valid = row < N;
    int rc = valid ? row : (N - 1);
    int s = __ldg(&g_rowptr[rc]);
    int e = valid ? __ldg(&g_rowptr[rc + 1]) : s;
    float4 sum = half_row_gather<true>(weight + q * 4, g_edge1, s, e, q);
    if (valid)
        *(float4*)(g_bufB + (size_t)rc * DIM + q * 4) = sum;
}

// ---------------------------------------------------------------------------
// Layer 2: bufB(h1) -> bufA(h2)
// ---------------------------------------------------------------------------
__global__ void __launch_bounds__(256, 8)
k_spmv2(int N) {
    int warp = (blockIdx.x * blockDim.x + threadIdx.x) >> 5;
    int lane = threadIdx.x & 31;
    int half = lane >> 4, q = lane & 15;
    int row = warp * 2 + half;
    bool valid = row < N;
    int rc = valid ? row : (N - 1);
    int s = __ldg(&g_rowptr[rc]);
    int e = valid ? __ldg(&g_rowptr[rc + 1]) : s;
    float4 sum = half_row_gather<false>(g_bufB + q * 4, g_edge, s, e, q);
    if (valid)
        *(float4*)(g_bufA + (size_t)rc * DIM + q * 4) = sum;
}

// ---------------------------------------------------------------------------
// Fused layer 3 + expmap0 + proj: warp handles rows {2w, 2w+1}.
//   h3 = A*h2 (gather bufA); acc = (h1+h2)+h3; final h -> bufB[row]
// ---------------------------------------------------------------------------
__global__ void __launch_bounds__(256, 8)
k_spmv3_final(int N) {
    int warp = (blockIdx.x * blockDim.x + threadIdx.x) >> 5;
    int lane = threadIdx.x & 31;
    int half = lane >> 4, q = lane & 15;
    int row = warp * 2 + half;
    bool valid = row < N;
    int rc = valid ? row : (N - 1);
    int s = __ldg(&g_rowptr[rc]);
    int e = valid ? __ldg(&g_rowptr[rc + 1]) : s;

    float4 h3 = half_row_gather<false>(g_bufA + q * 4, g_edge, s, e, q);

    size_t off = (size_t)rc * DIM + q * 4;
    const float4 h1 = *(const float4*)(g_bufB + off);
    const float4 h2 = *(const float4*)(g_bufA + off);
    float ax = (h1.x + h2.x) + h3.x;
    float ay = (h1.y + h2.y) + h3.y;
    float az = (h1.z + h2.z) + h3.z;
    float aw = (h1.w + h2.w) + h3.w;

    float x0 = (q == 0) ? 0.0f : ax;   // dim0 = x of q==0
    float n2 = halfAllSum(x0 * x0 + ay * ay + az * az + aw * aw);
    float xn = fmaxf(sqrtf(n2), 1e-15f);
    float sc = sinhf(xn) / xn;
    float r0 = x0 * sc, r1 = ay * sc, r2 = az * sc, r3 = aw * sc;
    float rn2 = halfAllSum(r0 * r0 + r1 * r1 + r2 * r2 + r3 * r3);
    float first = sqrtf(1.0f + rn2);
    if (valid) {
        float4 o;
        o.x = (q == 0) ? first : r0;
        o.y = r1; o.z = r2; o.w = r3;
        *(float4*)(g_bufB + off) = o;
    }
}

// ---------------------------------------------------------------------------
// loss: HALF-WARP PER PAIR, lane q owns dims [4q..4q+3] (float4).
// Hard-negative argmin: groups of 4 with independent reduction chains,
// scalar (best_d, best_j), single re-gather of winner. Strict < = first-min.
// ---------------------------------------------------------------------------
__device__ __forceinline__ float neg_d2(const float* __restrict__ h, int ni,
                                        float4 pv) {
    float4 nv = *(const float4*)(h + (size_t)ni * DIM);
    float dx = nv.x - pv.x, dy = nv.y - pv.y;
    float dz = nv.z - pv.z, dw = nv.w - pv.w;
    return dx * dx + dy * dy + dz * dz + dw * dw;
}

__global__ void __launch_bounds__(256, 6)
k_loss(const int* __restrict__ anchor, const int* __restrict__ pos,
       const int* __restrict__ neg, int M, int numNeg,
       float* __restrict__ out) {
    int tid  = threadIdx.x;
    int lane = tid & 31;
    int wib  = tid >> 5;
    int half = lane >> 4, q = lane & 15;
    int base = half << 4;
    int warp = blockIdx.x * 8 + wib;
    int m = warp * 2 + half;
    __shared__ float partial[8];

    float contrib = 0.0f;
    if (m < M) {
        const float* __restrict__ h = g_bufB + q * 4;
        int ai = __ldg(&anchor[m]);
        int pi = __ldg(&pos[m]);
        float4 av = *(const float4*)(h + (size_t)ai * DIM);
        float4 pv = *(const float4*)(h + (size_t)pi * DIM);
        float dotap = halfAllSum(av.x * pv.x + av.y * pv.y + av.z * pv.z + av.w * pv.w);
        float a0 = __shfl_sync(0xffffffffu, av.x, base);  // dim0 lives in q==0 .x
        float p0 = __shfl_sync(0xffffffffu, pv.x, base);
        float mink = dotap - 2.0f * a0 * p0;
        float th   = fmaxf(-mink, 1.0f + 1e-7f);
        float ac   = acoshf(th);
        float pos_score = fminf(ac * ac, 50.0f);

        float score = (1.0f - mink - a0 - p0) / (a0 * p0);
        float w = 1.0f / (1.0f + expf(score));   // sigmoid(-score)

        const int* nrow = neg + (size_t)m * numNeg;
        float best = 3.4e38f;
        int bestj = 0;
        if (numNeg == 16) {
#pragma unroll
            for (int g = 0; g < 16; g += 4) {
                int n0 = __ldg(&nrow[g]);
                int n1 = __ldg(&nrow[g + 1]);
                int n2i = __ldg(&nrow[g + 2]);
                int n3 = __ldg(&nrow[g + 3]);
                float pd0 = neg_d2(h, n0, pv);
                float pd1 = neg_d2(h, n1, pv);
                float pd2 = neg_d2(h, n2i, pv);
                float pd3 = neg_d2(h, n3, pv);
                float d0 = halfAllSum(pd0);   // independent chains: pipeline
                float d1 = halfAllSum(pd1);
                float d2 = halfAllSum(pd2);
                float d3 = halfAllSum(pd3);
                if (d0 < best) { best = d0; bestj = g; }
                if (d1 < best) { best = d1; bestj = g + 1; }
                if (d2 < best) { best = d2; bestj = g + 2; }
                if (d3 < best) { best = d3; bestj = g + 3; }
            }
        } else {
            for (int j = 0; j < numNeg; j++) {
                float d = halfAllSum(neg_d2(h, __ldg(&nrow[j]), pv));
                if (d < best) { best = d; bestj = j; }
            }
        }
        int nb = __ldg(&nrow[bestj]);
        float4 bv = *(const float4*)(h + (size_t)nb * DIM);
        float dotan = halfAllSum(av.x * bv.x + av.y * bv.y + av.z * bv.z + av.w * bv.w);
        float n0f = __shfl_sync(0xffffffffu, bv.x, base);
        float minkn = dotan - 2.0f * a0 * n0f;
        float thn = fmaxf(-minkn, 1.0f + 1e-7f);
        float acn = acoshf(thn);
        float neg_score = fminf(acn * acn, 50.0f);

        contrib = fmaxf(pos_score - neg_score + 0.1f * w, 0.0f);
    }
    contrib += __shfl_xor_sync(0xffffffffu, contrib, 16);  // fold halves
    if (lane == 0) partial[wib] = contrib;
    __syncthreads();
    if (tid == 0) {
        float s = 0.0f;
#pragma unroll
        for (int i = 0; i < 8; i++) s += partial[i];
        atomicAdd(out, s);
    }
}

// ---------------------------------------------------------------------------
extern "C" void kernel_launch(void* const* d_in, const int* in_sizes, int n_in,
                              void* d_out, int out_size) {
    const float* weight   = (const float*)d_in[0];
    const float* adj_vals = (const float*)d_in[1];
    const int*   adj_row  = (const int*)d_in[2];
    const int*   adj_col  = (const int*)d_in[3];
    const int*   anchor   = (const int*)d_in[4];
    const int*   pos      = (const int*)d_in[5];
    const int*   neg      = (const int*)d_in[6];
    float* out = (float*)d_out;

    int N = in_sizes[0] / DIM;         // 200000
    int E = in_sizes[1];               // 1.6M
    int M = in_sizes[4];               // 65536
    int numNeg = (M > 0) ? in_sizes[6] / M : 16;

    const int TPB = 256;               // 8 warps per block
    int scaleBlocks = (N + 7) / 8;     // warp per node
    int packElems   = E;
    if (packElems < N + 1) packElems = N + 1;
    if (packElems < out_size) packElems = out_size;
    int packBlocks  = (packElems + TPB - 1) / TPB;
    int spmvWarps   = (N + 1) / 2;     // warp per 2 rows
    int spmvBlocks  = (spmvWarps + 7) / 8;
    int lossWarps   = (M + 1) / 2;     // warp per 2 pairs
    int lossBlocks  = (lossWarps + 7) / 8;

    k_scale<<<scaleBlocks, TPB>>>(weight, N);
    k_pack<<<packBlocks, TPB>>>(adj_row, adj_col, adj_vals, N, E, out, out_size);
    k_spmv1<<<spmvBlocks, TPB>>>(weight, N);        // weight -> B(h1)
    k_spmv2<<<spmvBlocks, TPB>>>(N);                // B(h1) -> A(h2)
    k_spmv3_final<<<spmvBlocks, TPB>>>(N);          // -> B(final h)
    k_loss<<<lossBlocks, TPB>>>(anchor, pos, neg, M, numNeg, out);
}